// round 5
// baseline (speedup 1.0000x reference)
#include <cuda_runtime.h>
#include <math.h>

#define B 4
#define L 2048
#define H 8
#define D 64
#define S 40
#define U 40
#define HD (H*D)
#define CHUNK 128
#define NCHUNK (L/CHUNK)     /* 16 scan chunks */
#define KCHUNK 512
#define NKC (L/KCHUNK)       /* 4 key chunks for M pass */
#define SCALE 0.125f         /* 1/sqrt(64) */

// scratch (allocation-free rule: __device__ globals)
__device__ float2 g_pM[B*H*NKC*L];        // per-(bh,kc,q) partial {max, sum}
__device__ int    g_top[B*H*U];
__device__ float  g_agg[B*H*NCHUNK*D];    // scan chunk aggregates
__device__ int    g_flag[B*H*NCHUNK];     // lookback flags

// ---------------------------------------------------------------------------
// Kernel 1: partial M over one key-chunk of 512 keys (128KB -> L1-resident).
// Block = (bh, kc). Warp per q-iteration; ballot+__fns compacts the ~10
// in-chunk samples into steps of 8 groups x 4 lanes (16 floats of D per lane).
// Also clears the scan lookback flags (runs before scan kernel in stream).
// ---------------------------------------------------------------------------
__global__ void compute_M_kernel(const float* __restrict__ Q,
                                 const float* __restrict__ K,
                                 const int*   __restrict__ idx) {
    int blk = blockIdx.x;            // bh*NKC + kc
    int kc  = blk & (NKC-1);
    int bh  = blk >> 2;
    int h   = bh & (H-1), b = bh >> 3;

    if (threadIdx.x < 4) g_flag[blk*4 + threadIdx.x] = 0;   // 128*4 = 512 flags

    int warp = threadIdx.x >> 5, lane = threadIdx.x & 31;
    int g = lane >> 2, sub = lane & 3;
    const size_t bhK = ((size_t)b*L)*HD + (size_t)h*D;

    for (int q = warp; q < L; q += 8) {
        const float4* qp = (const float4*)(Q + ((size_t)b*L + q)*HD + (size_t)h*D) + sub*4;
        float4 q0 = qp[0], q1 = qp[1], q2 = qp[2], q3 = qp[3];

        int k0v = __ldg(idx + q*S + lane);
        int k1v = (lane < 8) ? __ldg(idx + q*S + 32 + lane) : -1;
        unsigned m0 = __ballot_sync(0xffffffffu, (k0v >> 9) == kc);
        unsigned m1 = __ballot_sync(0xffffffffu, (lane < 8) && ((k1v >> 9) == kc));
        int p0  = __popc(m0);
        int cnt = p0 + __popc(m1);

        float mx = -INFINITY, sm = 0.f;
        for (int bj = 0; bj < cnt; bj += 8) {
            int j = bj + g;
            bool valid = (j < cnt);
            int jj = valid ? j : 0;
            unsigned src;
            bool first = (jj < p0);
            if (first) src = __fns(m0, 0, jj + 1);
            else       src = __fns(m1, 0, jj - p0 + 1);
            int ka = __shfl_sync(0xffffffffu, k0v, (int)(src & 31));
            int kb = __shfl_sync(0xffffffffu, k1v, (int)(src & 31));
            int kk = first ? ka : kb;

            const float4* kp = (const float4*)(K + bhK + (size_t)kk*HD) + sub*4;
            float4 a0 = kp[0], a1 = kp[1], a2 = kp[2], a3 = kp[3];
            float p = q0.x*a0.x + q0.y*a0.y + q0.z*a0.z + q0.w*a0.w
                    + q1.x*a1.x + q1.y*a1.y + q1.z*a1.z + q1.w*a1.w
                    + q2.x*a2.x + q2.y*a2.y + q2.z*a2.z + q2.w*a2.w
                    + q3.x*a3.x + q3.y*a3.y + q3.z*a3.z + q3.w*a3.w;
            p += __shfl_xor_sync(0xffffffffu, p, 1);
            p += __shfl_xor_sync(0xffffffffu, p, 2);
            if (valid) { mx = fmaxf(mx, p); sm += p; }
        }
        #pragma unroll
        for (int o = 4; o <= 16; o <<= 1) {
            mx = fmaxf(mx, __shfl_xor_sync(0xffffffffu, mx, o));
            sm += __shfl_xor_sync(0xffffffffu, sm, o);
        }
        if (lane == 0) g_pM[(size_t)blk*L + q] = make_float2(mx, sm);
    }
}

// ---------------------------------------------------------------------------
// Kernel 2: combine chunk partials -> M, then top-40 per (b,h).
// One warp per (b,h); register-resident order-preserving uint32 values,
// packed (val, ~idx) u64 butterfly max; loser lane rescans its 64 slots.
// ---------------------------------------------------------------------------
__device__ __forceinline__ unsigned order_f32(float v) {
    unsigned u = __float_as_uint(v);
    return (u & 0x80000000u) ? ~u : (u | 0x80000000u);
}

__global__ void topk_kernel() {
    int bh   = blockIdx.x;
    int lane = threadIdx.x;           // block = 32
    const float2* P = g_pM + (size_t)bh*NKC*L;

    unsigned ov[64];
    #pragma unroll
    for (int j = 0; j < 64; j++) {
        int q = j*32 + lane;
        float2 c0 = P[0*L + q], c1 = P[1*L + q], c2 = P[2*L + q], c3 = P[3*L + q];
        float mx = fmaxf(fmaxf(c0.x, c1.x), fmaxf(c2.x, c3.x));
        float sm = (c0.y + c1.y) + (c2.y + c3.y);
        ov[j] = order_f32(mx - sm * (1.0f/(float)L));
    }

    unsigned long long removed = 0ull;
    unsigned bv = 0; int bslot = 0;
    #pragma unroll
    for (int j = 0; j < 64; j++) if (ov[j] > bv) { bv = ov[j]; bslot = j; }

    for (int u = 0; u < U; u++) {
        unsigned long long key =
            ((unsigned long long)bv << 32) | (unsigned)(~(unsigned)(bslot*32 + lane));
        #pragma unroll
        for (int o = 16; o > 0; o >>= 1) {
            unsigned long long ok = __shfl_xor_sync(0xffffffffu, key, o);
            if (ok > key) key = ok;
        }
        int widx = (int)(~(unsigned)key);
        if (lane == 0) g_top[bh*U + u] = widx;
        if ((widx & 31) == lane) {
            removed |= 1ull << (widx >> 5);
            bv = 0; bslot = 0;
            #pragma unroll
            for (int j = 0; j < 64; j++) {
                unsigned v = ((removed >> j) & 1ull) ? 0u : ov[j];
                if (v > bv) { bv = v; bslot = j; }
            }
        }
    }
}

// ---------------------------------------------------------------------------
// Kernel 3: fused cumsum(V) over L via decoupled lookback. One kernel, one V
// read, one out write. Block = (bh, c); all 512 blocks resident in one wave.
// ---------------------------------------------------------------------------
__global__ void scan_kernel(const float* __restrict__ V, float* __restrict__ out) {
    int blk = blockIdx.x;
    int c   = blk % NCHUNK;
    int bh  = blk / NCHUNK;
    int h   = bh & (H-1), b = bh >> 3;
    int t   = threadIdx.x;            // 256
    __shared__ float tile[CHUNK*D];   // 32KB
    __shared__ float part[4][64];
    __shared__ float offs[4][64];

    size_t base = (((size_t)b*L + (size_t)c*CHUNK))*HD + (size_t)h*D;
    for (int e = t; e < CHUNK*D/4; e += 256) {
        int q = e >> 4, d4 = e & 15;
        ((float4*)tile)[q*16 + d4] = *(const float4*)(V + base + (size_t)q*HD + d4*4);
    }
    __syncthreads();

    // intra-part serial scan: 4 parts x 64 d-lanes, 32 rows each
    int p = t >> 6, d = t & 63;
    {
        float acc = 0.f;
        #pragma unroll
        for (int i = 0; i < 32; i++) {
            acc += tile[(p*32 + i)*64 + d];
            tile[(p*32 + i)*64 + d] = acc;
        }
        part[p][d] = acc;
    }
    __syncthreads();

    // publish chunk aggregate (release)
    if (t < 64) g_agg[blk*D + t] = part[0][t] + part[1][t] + part[2][t] + part[3][t];
    __syncthreads();
    if (t == 0) { __threadfence(); atomicExch(&g_flag[blk], 1); }

    // lookback: wait for all predecessors, then sum their aggregates
    if (t < c) while (atomicAdd(&g_flag[bh*NCHUNK + t], 0) == 0) {}
    __syncthreads();
    __threadfence();
    if (t < 64) {
        float o = 0.f;
        for (int cc = 0; cc < c; cc++) o += g_agg[(bh*NCHUNK + cc)*D + t];
        offs[0][t] = o;          o += part[0][t];
        offs[1][t] = o;          o += part[1][t];
        offs[2][t] = o;          o += part[2][t];
        offs[3][t] = o;
    }
    __syncthreads();

    for (int e = t; e < CHUNK*D/4; e += 256) {
        int q = e >> 4, d4 = e & 15;
        float4 v  = ((float4*)tile)[q*16 + d4];
        float4 of = *(float4*)&offs[q >> 5][d4*4];
        v.x += of.x; v.y += of.y; v.z += of.z; v.w += of.w;
        *(float4*)(out + base + (size_t)q*HD + d4*4) = v;
    }
}

// ---------------------------------------------------------------------------
// Kernel 4: attention for the 40 selected queries per (b,h); scatter into out.
// Rank-i row attends only keys 0..i (Informer mask quirk: mask is triu(u,L)).
// ---------------------------------------------------------------------------
__global__ void attn_kernel(const float* __restrict__ Q,
                            const float* __restrict__ K,
                            const float* __restrict__ V,
                            float* __restrict__ out) {
    int bh = blockIdx.x;
    int h  = bh & (H-1), b = bh >> 3;
    int t  = threadIdx.x;     // 256 = 8 warps
    __shared__ float Ks[U][D], Vs[U][D], Qs[U][D];
    __shared__ int ti[U];

    if (t < U) ti[t] = g_top[bh*U + t];
    __syncthreads();

    for (int e = t; e < U*D; e += 256) {
        int r = e / D, d = e % D;
        Ks[r][d] = K[(((size_t)b*L + r)*H + h)*D + d];
        Vs[r][d] = V[(((size_t)b*L + r)*H + h)*D + d];
        Qs[r][d] = Q[(((size_t)b*L + ti[r])*H + h)*D + d];
    }
    __syncthreads();

    int warp = t >> 5, lane = t & 31;
    for (int i = warp; i < U; i += 8) {
        float2 qv = ((const float2*)Qs[i])[lane];
        float sc[U];
        float mx = -INFINITY;
        for (int k = 0; k <= i; k++) {
            float2 kv = ((const float2*)Ks[k])[lane];
            float p = qv.x*kv.x + qv.y*kv.y;
            #pragma unroll
            for (int o = 16; o > 0; o >>= 1) p += __shfl_xor_sync(0xffffffffu, p, o);
            p *= SCALE;
            sc[k] = p;
            mx = fmaxf(mx, p);
        }
        float denom = 0.f;
        for (int k = 0; k <= i; k++) { sc[k] = expf(sc[k] - mx); denom += sc[k]; }
        float inv = 1.f / denom;
        float2 acc = make_float2(0.f, 0.f);
        for (int k = 0; k <= i; k++) {
            float2 vv = ((const float2*)Vs[k])[lane];
            float w = sc[k] * inv;
            acc.x += w*vv.x;
            acc.y += w*vv.y;
        }
        ((float2*)(out + (((size_t)b*L + ti[i])*H + h)*D))[lane] = acc;
    }
}

// ---------------------------------------------------------------------------
extern "C" void kernel_launch(void* const* d_in, const int* in_sizes, int n_in,
                              void* d_out, int out_size) {
    const float* Q   = (const float*)d_in[0];
    const float* K   = (const float*)d_in[1];
    const float* V   = (const float*)d_in[2];
    const int*   idx = (const int*)d_in[3];
    float* out = (float*)d_out;

    // 1: partial M scores per key-chunk (also clears scan flags)
    compute_M_kernel<<<B*H*NKC, 256>>>(Q, K, idx);
    // 2: combine partials + top-40 per (b,h)
    topk_kernel<<<B*H, 32>>>();
    // 3: fused single-pass cumsum of V (decoupled lookback)
    scan_kernel<<<B*H*NCHUNK, 256>>>(V, out);
    // 4: sparse attention + scatter (after cumsum writes)
    attn_kernel<<<B*H, 256>>>(Q, K, V, out);
}

// round 6
// speedup vs baseline: 1.5331x; 1.5331x over previous
#include <cuda_runtime.h>
#include <math.h>

#define B 4
#define L 2048
#define H 8
#define D 64
#define S 40
#define U 40
#define HD (H*D)
#define CHUNK 128
#define NCHUNK (L/CHUNK)     /* 16 scan chunks */
#define KCHUNK 512
#define NKC (L/KCHUNK)       /* 4 key chunks for M pass */
#define QT 8                 /* query tiles for M pass */
#define QTILE (L/QT)         /* 256 queries per tile */
#define SCALE 0.125f         /* 1/sqrt(64) */

// scratch (allocation-free rule: __device__ globals)
__device__ float2 g_pM[B*H*NKC*L];        // per-(bh,kc,q) partial {max, sum}
__device__ int    g_top[B*H*U];
__device__ float  g_agg[B*H*NCHUNK*D];    // scan chunk aggregates
__device__ int    g_flag[B*H*NCHUNK];     // lookback flags

// ---------------------------------------------------------------------------
// Kernel 1: partial M over one key-chunk of 512 keys (128KB -> L1-resident).
// Grid = (bh, kc, qtile) = 1024 blocks; warp handles 32 consecutive queries.
// Ballot+__fns compacts the ~10 in-chunk samples into steps of 8 groups x 4
// lanes (16 floats of D per lane). Also clears the scan lookback flags.
// ---------------------------------------------------------------------------
__global__ void compute_M_kernel(const float* __restrict__ Q,
                                 const float* __restrict__ K,
                                 const int*   __restrict__ idx) {
    int blk  = blockIdx.x;               // ((bh*NKC)+kc)*QT + qt
    int qt   = blk & (QT-1);
    int kcbh = blk >> 3;
    int kc   = kcbh & (NKC-1);
    int bh   = kcbh >> 2;
    int h    = bh & (H-1), b = bh >> 3;

    if (threadIdx.x == 0 && blk < B*H*NCHUNK) g_flag[blk] = 0;

    int warp = threadIdx.x >> 5, lane = threadIdx.x & 31;
    int g = lane >> 2, sub = lane & 3;
    const size_t bhK = ((size_t)b*L)*HD + (size_t)h*D;
    int pblk = bh*NKC + kc;
    int qbase = qt*QTILE + warp*32;

    #pragma unroll 1
    for (int qi = 0; qi < 32; qi++) {
        int q = qbase + qi;
        const float4* qp = (const float4*)(Q + ((size_t)b*L + q)*HD + (size_t)h*D) + sub*4;
        float4 q0 = qp[0], q1 = qp[1], q2 = qp[2], q3 = qp[3];

        int k0v = __ldg(idx + q*S + lane);
        int k1v = (lane < 8) ? __ldg(idx + q*S + 32 + lane) : -1;
        unsigned m0 = __ballot_sync(0xffffffffu, (k0v >> 9) == kc);
        unsigned m1 = __ballot_sync(0xffffffffu, (lane < 8) && ((k1v >> 9) == kc));
        int p0  = __popc(m0);
        int cnt = p0 + __popc(m1);

        float mx = -INFINITY, sm = 0.f;
        for (int bj = 0; bj < cnt; bj += 8) {
            int j = bj + g;
            bool valid = (j < cnt);
            int jj = valid ? j : 0;
            unsigned src;
            bool first = (jj < p0);
            if (first) src = __fns(m0, 0, jj + 1);
            else       src = __fns(m1, 0, jj - p0 + 1);
            int ka = __shfl_sync(0xffffffffu, k0v, (int)(src & 31));
            int kb = __shfl_sync(0xffffffffu, k1v, (int)(src & 31));
            int kk = first ? ka : kb;

            const float4* kp = (const float4*)(K + bhK + (size_t)kk*HD) + sub*4;
            float4 a0 = kp[0], a1 = kp[1], a2 = kp[2], a3 = kp[3];
            float p = q0.x*a0.x + q0.y*a0.y + q0.z*a0.z + q0.w*a0.w
                    + q1.x*a1.x + q1.y*a1.y + q1.z*a1.z + q1.w*a1.w
                    + q2.x*a2.x + q2.y*a2.y + q2.z*a2.z + q2.w*a2.w
                    + q3.x*a3.x + q3.y*a3.y + q3.z*a3.z + q3.w*a3.w;
            p += __shfl_xor_sync(0xffffffffu, p, 1);
            p += __shfl_xor_sync(0xffffffffu, p, 2);
            if (valid) { mx = fmaxf(mx, p); sm += p; }
        }
        #pragma unroll
        for (int o = 4; o <= 16; o <<= 1) {
            mx = fmaxf(mx, __shfl_xor_sync(0xffffffffu, mx, o));
            sm += __shfl_xor_sync(0xffffffffu, sm, o);
        }
        if (lane == 0) g_pM[(size_t)pblk*L + q] = make_float2(mx, sm);
    }
}

// ---------------------------------------------------------------------------
// Kernel 2: combine chunk partials -> M, then top-40 per (b,h).
// One warp per (b,h); register-resident order-preserving uint32 values,
// packed (val, ~idx) u64 butterfly max; loser lane rescans its 64 slots.
// ---------------------------------------------------------------------------
__device__ __forceinline__ unsigned order_f32(float v) {
    unsigned u = __float_as_uint(v);
    return (u & 0x80000000u) ? ~u : (u | 0x80000000u);
}

__global__ void topk_kernel() {
    int bh   = blockIdx.x;
    int lane = threadIdx.x;           // block = 32
    const float2* P = g_pM + (size_t)bh*NKC*L;

    unsigned ov[64];
    #pragma unroll
    for (int j = 0; j < 64; j++) {
        int q = j*32 + lane;
        float2 c0 = P[0*L + q], c1 = P[1*L + q], c2 = P[2*L + q], c3 = P[3*L + q];
        float mx = fmaxf(fmaxf(c0.x, c1.x), fmaxf(c2.x, c3.x));
        float sm = (c0.y + c1.y) + (c2.y + c3.y);
        ov[j] = order_f32(mx - sm * (1.0f/(float)L));
    }

    unsigned long long removed = 0ull;
    unsigned bv = 0; int bslot = 0;
    #pragma unroll
    for (int j = 0; j < 64; j++) if (ov[j] > bv) { bv = ov[j]; bslot = j; }

    for (int u = 0; u < U; u++) {
        unsigned long long key =
            ((unsigned long long)bv << 32) | (unsigned)(~(unsigned)(bslot*32 + lane));
        #pragma unroll
        for (int o = 16; o > 0; o >>= 1) {
            unsigned long long ok = __shfl_xor_sync(0xffffffffu, key, o);
            if (ok > key) key = ok;
        }
        int widx = (int)(~(unsigned)key);
        if (lane == 0) g_top[bh*U + u] = widx;
        if ((widx & 31) == lane) {
            removed |= 1ull << (widx >> 5);
            bv = 0; bslot = 0;
            #pragma unroll
            for (int j = 0; j < 64; j++) {
                unsigned v = ((removed >> j) & 1ull) ? 0u : ov[j];
                if (v > bv) { bv = v; bslot = j; }
            }
        }
    }
}

// ---------------------------------------------------------------------------
// Kernel 3: fused cumsum(V) over L via decoupled lookback. One kernel, one V
// read, one out write. Block = (bh, c); all 512 blocks resident in one wave.
// ---------------------------------------------------------------------------
__global__ void scan_kernel(const float* __restrict__ V, float* __restrict__ out) {
    int blk = blockIdx.x;
    int c   = blk % NCHUNK;
    int bh  = blk / NCHUNK;
    int h   = bh & (H-1), b = bh >> 3;
    int t   = threadIdx.x;            // 256
    __shared__ float tile[CHUNK*D];   // 32KB
    __shared__ float part[4][64];
    __shared__ float offs[4][64];

    size_t base = (((size_t)b*L + (size_t)c*CHUNK))*HD + (size_t)h*D;
    for (int e = t; e < CHUNK*D/4; e += 256) {
        int q = e >> 4, d4 = e & 15;
        ((float4*)tile)[q*16 + d4] = *(const float4*)(V + base + (size_t)q*HD + d4*4);
    }
    __syncthreads();

    // intra-part serial scan: 4 parts x 64 d-lanes, 32 rows each
    int p = t >> 6, d = t & 63;
    {
        float acc = 0.f;
        #pragma unroll
        for (int i = 0; i < 32; i++) {
            acc += tile[(p*32 + i)*64 + d];
            tile[(p*32 + i)*64 + d] = acc;
        }
        part[p][d] = acc;
    }
    __syncthreads();

    // publish chunk aggregate (release)
    if (t < 64) g_agg[blk*D + t] = part[0][t] + part[1][t] + part[2][t] + part[3][t];
    __syncthreads();
    if (t == 0) { __threadfence(); atomicExch(&g_flag[blk], 1); }

    // lookback: wait for all predecessors, then sum their aggregates
    if (t < c) while (atomicAdd(&g_flag[bh*NCHUNK + t], 0) == 0) {}
    __syncthreads();
    __threadfence();
    if (t < 64) {
        float o = 0.f;
        for (int cc = 0; cc < c; cc++) o += g_agg[(bh*NCHUNK + cc)*D + t];
        offs[0][t] = o;          o += part[0][t];
        offs[1][t] = o;          o += part[1][t];
        offs[2][t] = o;          o += part[2][t];
        offs[3][t] = o;
    }
    __syncthreads();

    for (int e = t; e < CHUNK*D/4; e += 256) {
        int q = e >> 4, d4 = e & 15;
        float4 v  = ((float4*)tile)[q*16 + d4];
        float4 of = *(float4*)&offs[q >> 5][d4*4];
        v.x += of.x; v.y += of.y; v.z += of.z; v.w += of.w;
        *(float4*)(out + base + (size_t)q*HD + d4*4) = v;
    }
}

// ---------------------------------------------------------------------------
// Kernel 4: attention for the 40 selected queries per (b,h); scatter into out.
// Rank-i row attends only keys 0..i (Informer mask quirk: mask is triu(u,L)).
// Lane-per-key scoring: lane k owns score(i,k) (and k+32), no shuffle trees.
// ---------------------------------------------------------------------------
__global__ void attn_kernel(const float* __restrict__ Q,
                            const float* __restrict__ K,
                            const float* __restrict__ V,
                            float* __restrict__ out) {
    int bh = blockIdx.x;
    int h  = bh & (H-1), b = bh >> 3;
    int t  = threadIdx.x;     // 256 = 8 warps
    __shared__ float Ks[U][D+1], Vs[U][D+1], Qs[U][D+1];
    __shared__ int ti[U];

    if (t < U) ti[t] = g_top[bh*U + t];
    __syncthreads();

    for (int e = t; e < U*D; e += 256) {
        int r = e >> 6, d = e & 63;
        Ks[r][d] = K[(((size_t)b*L + r)*H + h)*D + d];
        Vs[r][d] = V[(((size_t)b*L + r)*H + h)*D + d];
        Qs[r][d] = Q[(((size_t)b*L + ti[r])*H + h)*D + d];
    }
    __syncthreads();

    int warp = t >> 5, lane = t & 31;
    int k2 = (lane < U-32) ? lane + 32 : lane;   // lanes 0..7 also own keys 32..39

    for (int i = warp; i < U; i += 8) {
        bool v0 = (lane <= i);
        bool v1 = (lane < U-32) && (lane + 32 <= i);

        float s0 = 0.f, s1 = 0.f;
        #pragma unroll
        for (int d = 0; d < D; d++) {
            float qd = Qs[i][d];
            s0 += qd * Ks[lane][d];
            s1 += qd * Ks[k2][d];
        }
        s0 *= SCALE; s1 *= SCALE;

        float mx = fmaxf(v0 ? s0 : -INFINITY, v1 ? s1 : -INFINITY);
        #pragma unroll
        for (int o = 16; o > 0; o >>= 1)
            mx = fmaxf(mx, __shfl_xor_sync(0xffffffffu, mx, o));

        float e0 = v0 ? __expf(s0 - mx) : 0.f;
        float e1 = v1 ? __expf(s1 - mx) : 0.f;
        float den = e0 + e1;
        #pragma unroll
        for (int o = 16; o > 0; o >>= 1)
            den += __shfl_xor_sync(0xffffffffu, den, o);
        float inv = __frcp_rn(den);
        float w0 = e0 * inv, w1 = e1 * inv;

        float a0 = 0.f, a1 = 0.f;
        int klim = (i < 31) ? i : 31;
        for (int k = 0; k <= klim; k++) {
            float w = __shfl_sync(0xffffffffu, w0, k);
            a0 += w * Vs[k][lane];
            a1 += w * Vs[k][lane+32];
        }
        for (int k = 32; k <= i; k++) {          // only when i >= 32
            float w = __shfl_sync(0xffffffffu, w1, k - 32);
            a0 += w * Vs[k][lane];
            a1 += w * Vs[k][lane+32];
        }

        float* op = out + (((size_t)b*L + ti[i])*H + h)*D;
        op[lane]      = a0;
        op[lane + 32] = a1;
    }
}

// ---------------------------------------------------------------------------
extern "C" void kernel_launch(void* const* d_in, const int* in_sizes, int n_in,
                              void* d_out, int out_size) {
    const float* Q   = (const float*)d_in[0];
    const float* K   = (const float*)d_in[1];
    const float* V   = (const float*)d_in[2];
    const int*   idx = (const int*)d_in[3];
    float* out = (float*)d_out;

    // 1: partial M scores per (key-chunk, query-tile); also clears scan flags
    compute_M_kernel<<<B*H*NKC*QT, 256>>>(Q, K, idx);
    // 2: combine partials + top-40 per (b,h)
    topk_kernel<<<B*H, 32>>>();
    // 3: fused single-pass cumsum of V (decoupled lookback)
    scan_kernel<<<B*H*NCHUNK, 256>>>(V, out);
    // 4: sparse attention + scatter (after cumsum writes)
    attn_kernel<<<B*H, 256>>>(Q, K, V, out);
}

// round 7
// speedup vs baseline: 4.5369x; 2.9593x over previous
#include <cuda_runtime.h>
#include <math.h>

#define B 4
#define L 2048
#define H 8
#define D 64
#define S 40
#define U 40
#define HD (H*D)
#define CHUNK 128
#define NCHUNK (L/CHUNK)     /* 16 scan chunks */
#define SCALE 0.125f         /* 1/sqrt(64) */

// scratch (allocation-free rule: __device__ globals)
__device__ float g_M[B*H*L];
__device__ int   g_top[B*H*U];
__device__ float g_agg[B*H*NCHUNK*D];    // scan chunk aggregates
__device__ int   g_flag[B*H*NCHUNK];     // lookback flags

// ---------------------------------------------------------------------------
// Kernel 1: M[b,h,q] = max_s dot(Q[b,h,q], K[b,h,idx[q,s]]) - sum_s/L
// One warp per (b,h,q). 4 groups of 8 lanes; each group owns one key per
// batch and reads its 256B row as 2x(8 lanes x 16B) = ONE 128B line per LDG
// (4 lines per gather instruction warp-wide). 10 batches of 4 keys.
// Also clears the scan lookback flags (runs first in stream).
// ---------------------------------------------------------------------------
__global__ void compute_M_kernel(const float* __restrict__ Q,
                                 const float* __restrict__ K,
                                 const int*   __restrict__ idx) {
    if (threadIdx.x == 0 && blockIdx.x < B*H*NCHUNK) g_flag[blockIdx.x] = 0;

    int gw   = (blockIdx.x * blockDim.x + threadIdx.x) >> 5;
    int lane = threadIdx.x & 31;
    if (gw >= B*H*L) return;
    int q = gw % L;
    int h = (gw / L) % H;
    int b = gw / (L*H);
    int g   = lane >> 3;     // group 0..3: which key in the batch
    int sub = lane & 7;      // 16B slice within the 128B half-row

    const float4* qrow = (const float4*)(Q + ((size_t)b*L + q)*HD + (size_t)h*D);
    float4 q0 = qrow[sub];        // dims [4*sub   .. 4*sub+3]
    float4 q1 = qrow[8 + sub];    // dims [32+4*sub .. ]

    int k0v = __ldg(idx + q*S + lane);
    int k1v = (lane < 8) ? __ldg(idx + q*S + 32 + lane) : 0;

    const size_t bhK = ((size_t)b*L)*HD + (size_t)h*D;

    float mx = -INFINITY, sm = 0.f;
    #pragma unroll
    for (int t = 0; t < 10; t++) {
        int srcl = t*4 + g;
        int kk = (srcl < 32) ? __shfl_sync(0xffffffffu, k0v, srcl)
                             : __shfl_sync(0xffffffffu, k1v, srcl - 32);
        const float4* krow = (const float4*)(K + bhK + (size_t)kk*HD);
        float4 k0 = krow[sub];
        float4 k1 = krow[8 + sub];
        float p = q0.x*k0.x + q0.y*k0.y + q0.z*k0.z + q0.w*k0.w
                + q1.x*k1.x + q1.y*k1.y + q1.z*k1.z + q1.w*k1.w;
        // reduce within the 8-lane group -> full 64-dim dot on every lane
        p += __shfl_xor_sync(0xffffffffu, p, 1);
        p += __shfl_xor_sync(0xffffffffu, p, 2);
        p += __shfl_xor_sync(0xffffffffu, p, 4);
        mx = fmaxf(mx, p);
        sm += p;
    }
    // reduce across the 4 groups
    mx = fmaxf(mx, __shfl_xor_sync(0xffffffffu, mx, 8));
    sm += __shfl_xor_sync(0xffffffffu, sm, 8);
    mx = fmaxf(mx, __shfl_xor_sync(0xffffffffu, mx, 16));
    sm += __shfl_xor_sync(0xffffffffu, sm, 16);

    if (lane == 0) g_M[gw] = mx - sm * (1.0f/(float)L);
}

// ---------------------------------------------------------------------------
// Kernel 2: top-40 per (b,h), descending, ties -> smaller index (lax.top_k).
// One warp per (b,h); register-resident order-preserving uint32 values,
// packed (val, ~idx) u64 butterfly max; loser lane rescans its 64 slots.
// ---------------------------------------------------------------------------
__device__ __forceinline__ unsigned order_f32(float v) {
    unsigned u = __float_as_uint(v);
    return (u & 0x80000000u) ? ~u : (u | 0x80000000u);
}

__global__ void topk_kernel() {
    int bh   = blockIdx.x;
    int lane = threadIdx.x;           // block = 32
    const float* M = g_M + bh*L;

    unsigned ov[64];
    #pragma unroll
    for (int j = 0; j < 64; j++) ov[j] = order_f32(M[j*32 + lane]);

    unsigned long long removed = 0ull;
    unsigned bv = 0; int bslot = 0;
    #pragma unroll
    for (int j = 0; j < 64; j++) if (ov[j] > bv) { bv = ov[j]; bslot = j; }

    for (int u = 0; u < U; u++) {
        unsigned long long key =
            ((unsigned long long)bv << 32) | (unsigned)(~(unsigned)(bslot*32 + lane));
        #pragma unroll
        for (int o = 16; o > 0; o >>= 1) {
            unsigned long long ok = __shfl_xor_sync(0xffffffffu, key, o);
            if (ok > key) key = ok;
        }
        int widx = (int)(~(unsigned)key);
        if (lane == 0) g_top[bh*U + u] = widx;
        if ((widx & 31) == lane) {
            removed |= 1ull << (widx >> 5);
            bv = 0; bslot = 0;
            #pragma unroll
            for (int j = 0; j < 64; j++) {
                unsigned v = ((removed >> j) & 1ull) ? 0u : ov[j];
                if (v > bv) { bv = v; bslot = j; }
            }
        }
    }
}

// ---------------------------------------------------------------------------
// Kernel 3: fused cumsum(V) over L via decoupled lookback. One kernel, one V
// read, one out write. Block = (bh, c); all 512 blocks resident in one wave.
// ---------------------------------------------------------------------------
__global__ void scan_kernel(const float* __restrict__ V, float* __restrict__ out) {
    int blk = blockIdx.x;
    int c   = blk % NCHUNK;
    int bh  = blk / NCHUNK;
    int h   = bh & (H-1), b = bh >> 3;
    int t   = threadIdx.x;            // 256
    __shared__ float tile[CHUNK*D];   // 32KB
    __shared__ float part[4][64];
    __shared__ float offs[4][64];

    size_t base = (((size_t)b*L + (size_t)c*CHUNK))*HD + (size_t)h*D;
    for (int e = t; e < CHUNK*D/4; e += 256) {
        int q = e >> 4, d4 = e & 15;
        ((float4*)tile)[q*16 + d4] = *(const float4*)(V + base + (size_t)q*HD + d4*4);
    }
    __syncthreads();

    // intra-part serial scan: 4 parts x 64 d-lanes, 32 rows each
    int p = t >> 6, d = t & 63;
    {
        float acc = 0.f;
        #pragma unroll
        for (int i = 0; i < 32; i++) {
            acc += tile[(p*32 + i)*64 + d];
            tile[(p*32 + i)*64 + d] = acc;
        }
        part[p][d] = acc;
    }
    __syncthreads();

    // publish chunk aggregate (release)
    if (t < 64) g_agg[blk*D + t] = part[0][t] + part[1][t] + part[2][t] + part[3][t];
    __syncthreads();
    if (t == 0) { __threadfence(); atomicExch(&g_flag[blk], 1); }

    // lookback: wait for all predecessors, then sum their aggregates
    if (t < c) while (atomicAdd(&g_flag[bh*NCHUNK + t], 0) == 0) {}
    __syncthreads();
    __threadfence();
    if (t < 64) {
        float o = 0.f;
        for (int cc = 0; cc < c; cc++) o += g_agg[(bh*NCHUNK + cc)*D + t];
        offs[0][t] = o;          o += part[0][t];
        offs[1][t] = o;          o += part[1][t];
        offs[2][t] = o;          o += part[2][t];
        offs[3][t] = o;
    }
    __syncthreads();

    for (int e = t; e < CHUNK*D/4; e += 256) {
        int q = e >> 4, d4 = e & 15;
        float4 v  = ((float4*)tile)[q*16 + d4];
        float4 of = *(float4*)&offs[q >> 5][d4*4];
        v.x += of.x; v.y += of.y; v.z += of.z; v.w += of.w;
        *(float4*)(out + base + (size_t)q*HD + d4*4) = v;
    }
}

// ---------------------------------------------------------------------------
// Kernel 4: attention for the 40 selected queries per (b,h); scatter into out.
// Rank-i row attends only keys 0..i (Informer mask quirk: mask is triu(u,L)).
// Grid = (bh, group of 8 rows) = 160 blocks; one warp per output row.
// Lane-per-key scoring: lane k owns score(i,k) (and k+32), no shuffle trees.
// ---------------------------------------------------------------------------
__global__ void attn_kernel(const float* __restrict__ Q,
                            const float* __restrict__ K,
                            const float* __restrict__ V,
                            float* __restrict__ out) {
    int g  = blockIdx.x % 5;
    int bh = blockIdx.x / 5;
    int h  = bh & (H-1), b = bh >> 3;
    int t  = threadIdx.x;     // 256 = 8 warps
    __shared__ float Ks[U][D+1], Vs[U][D+1], Qs[8][D+1];
    __shared__ int ti[U];

    if (t < U) ti[t] = g_top[bh*U + t];
    __syncthreads();

    for (int e = t; e < U*D; e += 256) {
        int r = e >> 6, d = e & 63;
        Ks[r][d] = K[(((size_t)b*L + r)*H + h)*D + d];
        Vs[r][d] = V[(((size_t)b*L + r)*H + h)*D + d];
    }
    for (int e = t; e < 8*D; e += 256) {
        int r = e >> 6, d = e & 63;
        Qs[r][d] = Q[(((size_t)b*L + ti[g*8 + r])*H + h)*D + d];
    }
    __syncthreads();

    int warp = t >> 5, lane = t & 31;
    int i  = g*8 + warp;                          // output row rank 0..39
    int k2 = (lane < U-32) ? lane + 32 : lane;    // lanes 0..7 also own keys 32..39

    bool v0 = (lane <= i);
    bool v1 = (lane < U-32) && (lane + 32 <= i);

    float s0 = 0.f, s1 = 0.f;
    #pragma unroll
    for (int d = 0; d < D; d++) {
        float qd = Qs[warp][d];
        s0 += qd * Ks[lane][d];
        s1 += qd * Ks[k2][d];
    }
    s0 *= SCALE; s1 *= SCALE;

    float mx = fmaxf(v0 ? s0 : -INFINITY, v1 ? s1 : -INFINITY);
    #pragma unroll
    for (int o = 16; o > 0; o >>= 1)
        mx = fmaxf(mx, __shfl_xor_sync(0xffffffffu, mx, o));

    float e0 = v0 ? __expf(s0 - mx) : 0.f;
    float e1 = v1 ? __expf(s1 - mx) : 0.f;
    float den = e0 + e1;
    #pragma unroll
    for (int o = 16; o > 0; o >>= 1)
        den += __shfl_xor_sync(0xffffffffu, den, o);
    float inv = __frcp_rn(den);
    float w0 = e0 * inv, w1 = e1 * inv;

    float a0 = 0.f, a1 = 0.f;
    int klim = (i < 31) ? i : 31;
    for (int k = 0; k <= klim; k++) {
        float w = __shfl_sync(0xffffffffu, w0, k);
        a0 += w * Vs[k][lane];
        a1 += w * Vs[k][lane+32];
    }
    for (int k = 32; k <= i; k++) {               // only when i >= 32
        float w = __shfl_sync(0xffffffffu, w1, k - 32);
        a0 += w * Vs[k][lane];
        a1 += w * Vs[k][lane+32];
    }

    float* op = out + (((size_t)b*L + ti[i])*H + h)*D;
    op[lane]      = a0;
    op[lane + 32] = a1;
}

// ---------------------------------------------------------------------------
extern "C" void kernel_launch(void* const* d_in, const int* in_sizes, int n_in,
                              void* d_out, int out_size) {
    const float* Q   = (const float*)d_in[0];
    const float* K   = (const float*)d_in[1];
    const float* V   = (const float*)d_in[2];
    const int*   idx = (const int*)d_in[3];
    float* out = (float*)d_out;

    // 1: M scores — one warp per (b,h,q); also clears scan flags
    compute_M_kernel<<<B*H*L*32/256, 256>>>(Q, K, idx);
    // 2: top-40 per (b,h) — one warp per (b,h)
    topk_kernel<<<B*H, 32>>>();
    // 3: fused single-pass cumsum of V (decoupled lookback)
    scan_kernel<<<B*H*NCHUNK, 256>>>(V, out);
    // 4: sparse attention + scatter (after cumsum writes)
    attn_kernel<<<B*H*5, 256>>>(Q, K, V, out);
}